// round 3
// baseline (speedup 1.0000x reference)
#include <cuda_runtime.h>
#include <cstdint>
#include <cstddef>

#define TS 1024
#define BB 64
#define HH 1024
#define G4 4096

__device__ float g_xproj[(size_t)TS * BB * G4];
__device__ float g_h[2][BB * HH];
__device__ unsigned g_count = 0;
__device__ unsigned g_gen = 0;

typedef unsigned long long ull;
__device__ __forceinline__ ull pack2(float a, float b) {
    ull r; asm("mov.b64 %0, {%1, %2};" : "=l"(r) : "f"(a), "f"(b)); return r;
}
__device__ __forceinline__ void unpack2(ull p, float& a, float& b) {
    asm("mov.b64 {%0, %1}, %2;" : "=f"(a), "=f"(b) : "l"(p));
}
__device__ __forceinline__ ull ffma2(ull a, ull b, ull c) {
    ull d; asm("fma.rn.f32x2 %0, %1, %2, %3;" : "=l"(d) : "l"(a), "l"(b), "l"(c)); return d;
}
__device__ __forceinline__ float sigf(float x) { return 1.0f / (1.0f + __expf(-x)); }

// ===================== Kernel 1: x_proj GEMM (128x128x16) =====================
__global__ __launch_bounds__(256) void xproj_kernel(
    const float* __restrict__ X, const float* __restrict__ Wih,
    const float* __restrict__ bih, const float* __restrict__ bhh)
{
    __shared__ float As[2][16][128];
    __shared__ float Bs[2][16][128];
    const int tid = threadIdx.x;
    const int m0 = blockIdx.y * 128, n0 = blockIdx.x * 128;
    const int lm = tid & 127, lq = tid >> 7;
    const float* Xrow = X + (size_t)(m0 + lm) * HH;
    const float* Wrow = Wih + (size_t)(n0 + lm) * HH;
    const int tx = tid & 15, ty = tid >> 4;

    ull acc[8][4];
#pragma unroll
    for (int r = 0; r < 8; r++)
#pragma unroll
        for (int j = 0; j < 4; j++) acc[r][j] = 0ull;

    float4 xa[2], xb[2];
#pragma unroll
    for (int u = 0; u < 2; u++) {
        xa[u] = *(const float4*)&Xrow[(lq + 2 * u) * 4];
        xb[u] = *(const float4*)&Wrow[(lq + 2 * u) * 4];
    }
    for (int kt = 0; kt < 64; ++kt) {
        const int cur = kt & 1;
#pragma unroll
        for (int u = 0; u < 2; u++) {
            const int kq = (lq + 2 * u) * 4;
            As[cur][kq + 0][lm] = xa[u].x; As[cur][kq + 1][lm] = xa[u].y;
            As[cur][kq + 2][lm] = xa[u].z; As[cur][kq + 3][lm] = xa[u].w;
            Bs[cur][kq + 0][lm] = xb[u].x; Bs[cur][kq + 1][lm] = xb[u].y;
            Bs[cur][kq + 2][lm] = xb[u].z; Bs[cur][kq + 3][lm] = xb[u].w;
        }
        __syncthreads();
        if (kt < 63) {
            const int kb = (kt + 1) * 16;
#pragma unroll
            for (int u = 0; u < 2; u++) {
                xa[u] = *(const float4*)&Xrow[kb + (lq + 2 * u) * 4];
                xb[u] = *(const float4*)&Wrow[kb + (lq + 2 * u) * 4];
            }
        }
#pragma unroll
        for (int k = 0; k < 16; k++) {
            const float4 a0 = *(const float4*)&As[cur][k][ty * 8];
            const float4 a1 = *(const float4*)&As[cur][k][ty * 8 + 4];
            const ulonglong2 b0 = *(const ulonglong2*)&Bs[cur][k][tx * 8];
            const ulonglong2 b1 = *(const ulonglong2*)&Bs[cur][k][tx * 8 + 4];
            const ull bp[4] = { b0.x, b0.y, b1.x, b1.y };
            const float av[8] = { a0.x, a0.y, a0.z, a0.w, a1.x, a1.y, a1.z, a1.w };
#pragma unroll
            for (int r = 0; r < 8; r++) {
                const ull ar = pack2(av[r], av[r]);
#pragma unroll
                for (int j = 0; j < 4; j++) acc[r][j] = ffma2(ar, bp[j], acc[r][j]);
            }
        }
        __syncthreads();
    }
    float bias[8];
#pragma unroll
    for (int j = 0; j < 8; j++) bias[j] = bih[n0 + tx * 8 + j] + bhh[n0 + tx * 8 + j];
#pragma unroll
    for (int r = 0; r < 8; r++) {
        float c[8];
        unpack2(acc[r][0], c[0], c[1]); unpack2(acc[r][1], c[2], c[3]);
        unpack2(acc[r][2], c[4], c[5]); unpack2(acc[r][3], c[6], c[7]);
        float* Crow = g_xproj + (size_t)(m0 + ty * 8 + r) * G4 + n0 + tx * 8;
#pragma unroll
        for (int j = 0; j < 8; j++) Crow[j] = c[j] + bias[j];
    }
}

// ===================== grid barrier =====================
__device__ __forceinline__ void grid_barrier()
{
    __syncthreads();
    if (threadIdx.x == 0) {
        __threadfence();
        const unsigned gen = *(volatile unsigned*)&g_gen;
        atomicAdd(&g_count, 1u);
        if (blockIdx.x == 0) {
            while (*(volatile unsigned*)&g_count != gridDim.x) { __nanosleep(64); }
            g_count = 0;
            __threadfence();
            atomicAdd(&g_gen, 1u);
        } else {
            while (*(volatile unsigned*)&g_gen == gen) { __nanosleep(64); }
        }
        __threadfence();
    }
    __syncthreads();
}

// ===================== Kernel 2: persistent recurrence =====================
// 128 CTAs x 256 threads. CTA owns h-cols [8*bid, 8*bid+8) for all 4 gates.
// Wsm: [1024][32] resident all steps. Hs: [2][64][36] k-tile double buffer.
#define WSM_FLOATS (1024 * 32)
#define HSB 2304   // 64*36

__global__ __launch_bounds__(256, 1) void lstm_rec_kernel(
    const float* __restrict__ Whh, const float* __restrict__ h0,
    const float* __restrict__ c0, float* __restrict__ out, size_t out_size)
{
    extern __shared__ float smem[];
    float* Wsm = smem;
    float* Hsm = smem + WSM_FLOATS;

    const int tid = threadIdx.x;
    const int j0 = blockIdx.x * 8;
    const int r = tid >> 2;          // batch row 0..63
    const int ppidx = tid & 3;       // col-pair 0..3
    const int jj0 = j0 + ppidx * 2;
    const int pp8 = ppidx * 8;

    // ---- load Whh slice into Wsm once. c = ppidx*8 + g*2 + half ----
    {
        const int c = tid >> 3, l8 = tid & 7;
        const int pi = c >> 3, rem = c & 7, g = rem >> 1, half = rem & 1;
        const int grow = g * HH + j0 + pi * 2 + half;
        const float* Wr = Whh + (size_t)grow * HH;
        for (int it = 0; it < 32; ++it) {
            const int k0 = (l8 + it * 8) * 4;
            const float4 v = *(const float4*)&Wr[k0];
            Wsm[(k0 + 0) * 32 + c] = v.x; Wsm[(k0 + 1) * 32 + c] = v.y;
            Wsm[(k0 + 2) * 32 + c] = v.z; Wsm[(k0 + 3) * 32 + c] = v.w;
        }
    }

    float2 c_reg = *(const float2*)&c0[(size_t)r * HH + jj0];

    int hB[2], hQ[2];
#pragma unroll
    for (int u = 0; u < 2; u++) {
        const int idx = tid + 256 * u;
        hB[u] = idx >> 3; hQ[u] = (idx & 7) * 4;
    }
    __syncthreads();

    const size_t hT_off = (size_t)TS * BB * HH;
    const bool wr_tail = out_size >= hT_off + 2 * (size_t)BB * HH;
    float2 hlast = make_float2(0.f, 0.f);

    for (int t = 0; t < TS; ++t) {
        const float* __restrict__ hsrc = (t == 0) ? h0 : g_h[(t + 1) & 1];

        float2 xp[4];
        {
            const float* xpr = g_xproj + ((size_t)t * BB + r) * G4;
#pragma unroll
            for (int g = 0; g < 4; g++)
                xp[g] = *(const float2*)&xpr[g * HH + jj0];
        }

        ull acc[4] = {0ull, 0ull, 0ull, 0ull};
        float4 hreg[2];
#pragma unroll
        for (int u = 0; u < 2; u++)
            hreg[u] = *(const float4*)&hsrc[(size_t)hB[u] * HH + hQ[u]];

        for (int kt = 0; kt < 32; ++kt) {
            const int cur = kt & 1;
            float* HsB = Hsm + cur * HSB;
#pragma unroll
            for (int u = 0; u < 2; u++)
                *(float4*)&HsB[hB[u] * 36 + hQ[u]] = hreg[u];
            __syncthreads();
            if (kt < 31) {
                const int kb = (kt + 1) * 32;
#pragma unroll
                for (int u = 0; u < 2; u++)
                    hreg[u] = *(const float4*)&hsrc[(size_t)hB[u] * HH + kb + hQ[u]];
            }
            const float* Hrow = Hsm + cur * HSB + r * 36;
            const float* Wk = Wsm + (size_t)kt * 32 * 32 + pp8;
#pragma unroll
            for (int k4 = 0; k4 < 8; k4++) {
                const float4 av = *(const float4*)&Hrow[k4 * 4];
                const float a[4] = { av.x, av.y, av.z, av.w };
#pragma unroll
                for (int i = 0; i < 4; i++) {
                    const ull aa = pack2(a[i], a[i]);
                    const float* wp = Wk + (k4 * 4 + i) * 32;
                    const ulonglong2 wa = *(const ulonglong2*)wp;
                    const ulonglong2 wb = *(const ulonglong2*)(wp + 4);
                    acc[0] = ffma2(aa, wa.x, acc[0]);
                    acc[1] = ffma2(aa, wa.y, acc[1]);
                    acc[2] = ffma2(aa, wb.x, acc[2]);
                    acc[3] = ffma2(aa, wb.y, acc[3]);
                }
            }
            __syncthreads();
        }

        // ---- LSTM cell (registers) ----
        float G[4][2];
#pragma unroll
        for (int g = 0; g < 4; g++) {
            float lo, hi; unpack2(acc[g], lo, hi);
            G[g][0] = lo + xp[g].x; G[g][1] = hi + xp[g].y;
        }
        float hv[2], cv[2] = { c_reg.x, c_reg.y };
#pragma unroll
        for (int j = 0; j < 2; j++) {
            const float iv = sigf(G[0][j]);
            const float fv = sigf(G[1][j]);
            const float gv = tanhf(G[2][j]);
            const float ov = sigf(G[3][j]);
            const float cn = fmaf(fv, cv[j], iv * gv);
            cv[j] = cn;
            hv[j] = ov * tanhf(cn);
        }
        c_reg = make_float2(cv[0], cv[1]);
        const float2 hp = make_float2(hv[0], hv[1]);
        hlast = hp;
        *(float2*)&g_h[t & 1][(size_t)r * HH + jj0] = hp;
        *(float2*)&out[((size_t)t * BB + r) * HH + jj0] = hp;

        grid_barrier();
    }

    if (wr_tail) {
        *(float2*)&out[hT_off + (size_t)r * HH + jj0] = hlast;
        *(float2*)&out[hT_off + (size_t)BB * HH + (size_t)r * HH + jj0] = c_reg;
    }
}

extern "C" void kernel_launch(void* const* d_in, const int* in_sizes, int n_in,
                              void* d_out, int out_size)
{
    const float* x   = (const float*)d_in[0];
    const float* Wih = (const float*)d_in[1];
    const float* Whh = (const float*)d_in[2];
    const float* bih = (const float*)d_in[3];
    const float* bhh = (const float*)d_in[4];
    const float* h0  = (const float*)d_in[5];
    const float* c0  = (const float*)d_in[6];
    float* out = (float*)d_out;

    dim3 g1(G4 / 128, (TS * BB) / 128);
    xproj_kernel<<<g1, 256>>>(x, Wih, bih, bhh);

    const int smem_bytes = (WSM_FLOATS + 2 * HSB) * sizeof(float);
    static bool attr_set = false;
    if (!attr_set) {
        cudaFuncSetAttribute(lstm_rec_kernel,
                             cudaFuncAttributeMaxDynamicSharedMemorySize, smem_bytes);
        attr_set = true;
    }
    lstm_rec_kernel<<<128, 256, smem_bytes>>>(Whh, h0, c0, out, (size_t)out_size);
}

// round 4
// speedup vs baseline: 1.4125x; 1.4125x over previous
#include <cuda_runtime.h>
#include <cstdint>
#include <cstddef>

#define TS 1024
#define BB 64
#define HH 1024
#define G4 4096

__device__ float g_xproj[(size_t)TS * BB * G4];
__device__ float g_h[2][BB * HH];
__device__ unsigned g_count = 0;
__device__ unsigned g_gen = 0;

typedef unsigned long long ull;
__device__ __forceinline__ ull pack2(float a, float b) {
    ull r; asm("mov.b64 %0, {%1, %2};" : "=l"(r) : "f"(a), "f"(b)); return r;
}
__device__ __forceinline__ void unpack2(ull p, float& a, float& b) {
    asm("mov.b64 {%0, %1}, %2;" : "=f"(a), "=f"(b) : "l"(p));
}
__device__ __forceinline__ ull ffma2(ull a, ull b, ull c) {
    ull d; asm("fma.rn.f32x2 %0, %1, %2, %3;" : "=l"(d) : "l"(a), "l"(b), "l"(c)); return d;
}
__device__ __forceinline__ float sigf(float x) { return 1.0f / (1.0f + __expf(-x)); }

// ===================== Kernel 1: x_proj GEMM (128x128x16) =====================
__global__ __launch_bounds__(256) void xproj_kernel(
    const float* __restrict__ X, const float* __restrict__ Wih,
    const float* __restrict__ bih, const float* __restrict__ bhh)
{
    __shared__ float As[2][16][128];
    __shared__ float Bs[2][16][128];
    const int tid = threadIdx.x;
    const int m0 = blockIdx.y * 128, n0 = blockIdx.x * 128;
    const int lm = tid & 127, lq = tid >> 7;
    const float* Xrow = X + (size_t)(m0 + lm) * HH;
    const float* Wrow = Wih + (size_t)(n0 + lm) * HH;
    const int tx = tid & 15, ty = tid >> 4;

    ull acc[8][4];
#pragma unroll
    for (int r = 0; r < 8; r++)
#pragma unroll
        for (int j = 0; j < 4; j++) acc[r][j] = 0ull;

    float4 xa[2], xb[2];
#pragma unroll
    for (int u = 0; u < 2; u++) {
        xa[u] = *(const float4*)&Xrow[(lq + 2 * u) * 4];
        xb[u] = *(const float4*)&Wrow[(lq + 2 * u) * 4];
    }
    for (int kt = 0; kt < 64; ++kt) {
        const int cur = kt & 1;
#pragma unroll
        for (int u = 0; u < 2; u++) {
            const int kq = (lq + 2 * u) * 4;
            As[cur][kq + 0][lm] = xa[u].x; As[cur][kq + 1][lm] = xa[u].y;
            As[cur][kq + 2][lm] = xa[u].z; As[cur][kq + 3][lm] = xa[u].w;
            Bs[cur][kq + 0][lm] = xb[u].x; Bs[cur][kq + 1][lm] = xb[u].y;
            Bs[cur][kq + 2][lm] = xb[u].z; Bs[cur][kq + 3][lm] = xb[u].w;
        }
        __syncthreads();
        if (kt < 63) {
            const int kb = (kt + 1) * 16;
#pragma unroll
            for (int u = 0; u < 2; u++) {
                xa[u] = *(const float4*)&Xrow[kb + (lq + 2 * u) * 4];
                xb[u] = *(const float4*)&Wrow[kb + (lq + 2 * u) * 4];
            }
        }
#pragma unroll
        for (int k = 0; k < 16; k++) {
            const float4 a0 = *(const float4*)&As[cur][k][ty * 8];
            const float4 a1 = *(const float4*)&As[cur][k][ty * 8 + 4];
            const ulonglong2 b0 = *(const ulonglong2*)&Bs[cur][k][tx * 8];
            const ulonglong2 b1 = *(const ulonglong2*)&Bs[cur][k][tx * 8 + 4];
            const ull bp[4] = { b0.x, b0.y, b1.x, b1.y };
            const float av[8] = { a0.x, a0.y, a0.z, a0.w, a1.x, a1.y, a1.z, a1.w };
#pragma unroll
            for (int r = 0; r < 8; r++) {
                const ull ar = pack2(av[r], av[r]);
#pragma unroll
                for (int j = 0; j < 4; j++) acc[r][j] = ffma2(ar, bp[j], acc[r][j]);
            }
        }
        __syncthreads();
    }
    float bias[8];
#pragma unroll
    for (int j = 0; j < 8; j++) bias[j] = bih[n0 + tx * 8 + j] + bhh[n0 + tx * 8 + j];
#pragma unroll
    for (int r = 0; r < 8; r++) {
        float c[8];
        unpack2(acc[r][0], c[0], c[1]); unpack2(acc[r][1], c[2], c[3]);
        unpack2(acc[r][2], c[4], c[5]); unpack2(acc[r][3], c[6], c[7]);
        float* Crow = g_xproj + (size_t)(m0 + ty * 8 + r) * G4 + n0 + tx * 8;
#pragma unroll
        for (int j = 0; j < 8; j++) Crow[j] = c[j] + bias[j];
    }
}

// ===================== grid barrier =====================
__device__ __forceinline__ void grid_barrier()
{
    __syncthreads();
    if (threadIdx.x == 0) {
        __threadfence();
        const unsigned gen = *(volatile unsigned*)&g_gen;
        atomicAdd(&g_count, 1u);
        if (blockIdx.x == 0) {
            while (*(volatile unsigned*)&g_count != gridDim.x) { __nanosleep(64); }
            g_count = 0;
            __threadfence();
            atomicAdd(&g_gen, 1u);
        } else {
            while (*(volatile unsigned*)&g_gen == gen) { __nanosleep(64); }
        }
        __threadfence();
    }
    __syncthreads();
}

// ===================== Kernel 2: persistent recurrence, W in registers ========
// 128 CTAs x 256 threads. CTA bid owns h-cols [8*bid, 8*bid+8) => 32 gate cols.
// Thread (cg = tid&3, kc = tid>>2): gate cg (8 cols), k-chunk [kc*16, kc*16+16).
// W slice = 128 floats/thread in registers for ALL 1024 steps.
__global__ __launch_bounds__(256, 1) void lstm_rec_kernel(
    const float* __restrict__ Whh, const float* __restrict__ h0,
    const float* __restrict__ c0, float* __restrict__ out, int out_size)
{
    __shared__ float red[8 * 8 * 36];   // [warp][b_local][36]
    __shared__ float gates[8 * 36];     // [b_local][36]
    __shared__ float csm[BB * 8];       // c state: [b][jl]

    const int tid = threadIdx.x;
    const int j0 = blockIdx.x * 8;
    const int cg = tid & 3;
    const int kc = tid >> 2;
    const int kb = kc * 16;
    const int lane = tid & 31;
    const int wid = tid >> 5;
    const int b_loc = (lane >> 2) & 7;  // kc low bits within warp

    // ---- c state into smem ----
    for (int i = tid; i < BB * 8; i += 256) {
        const int b = i >> 3, jl = i & 7;
        csm[i] = c0[(size_t)b * HH + j0 + jl];
    }

    // ---- W_hh slice into registers (once) ----
    ull wreg[16][4];
#pragma unroll
    for (int p = 0; p < 4; p++) {
        const float* r0 = Whh + (size_t)(cg * HH + j0 + 2 * p) * HH + kb;
        const float* r1 = r0 + HH;
        float w0[16], w1[16];
#pragma unroll
        for (int q = 0; q < 4; q++) {
            const float4 a = *(const float4*)&r0[q * 4];
            const float4 b4 = *(const float4*)&r1[q * 4];
            w0[q*4+0] = a.x;  w0[q*4+1] = a.y;  w0[q*4+2] = a.z;  w0[q*4+3] = a.w;
            w1[q*4+0] = b4.x; w1[q*4+1] = b4.y; w1[q*4+2] = b4.z; w1[q*4+3] = b4.w;
        }
#pragma unroll
        for (int k = 0; k < 16; k++) wreg[k][p] = pack2(w0[k], w1[k]);
    }
    __syncthreads();

    const int hT = TS * BB * HH;
    const bool wr_tail = out_size >= hT + 2 * BB * HH;

    for (int t = 0; t < TS; ++t) {
        const float* __restrict__ hsrc = (t == 0) ? h0 : g_h[(t + 1) & 1];
        float* __restrict__ hdst = g_h[t & 1];

        float4 hbuf[2][4];
#pragma unroll
        for (int u = 0; u < 2; u++) {
            const float4* hp = (const float4*)(hsrc + (size_t)u * HH + kb);
#pragma unroll
            for (int q = 0; q < 4; q++) hbuf[u][q] = __ldcg(hp + q);
        }

        for (int grp = 0; grp < 8; ++grp) {
            ull acc[8][4];
#pragma unroll
            for (int bl = 0; bl < 8; bl++)
#pragma unroll
                for (int p = 0; p < 4; p++) acc[bl][p] = 0ull;

#pragma unroll
            for (int bl = 0; bl < 8; bl++) {
                float4 hc[4];
#pragma unroll
                for (int q = 0; q < 4; q++) hc[q] = hbuf[bl & 1][q];
                const int pb = grp * 8 + bl + 2;       // prefetch 2 ahead
                if (pb < BB) {
                    const float4* hp = (const float4*)(hsrc + (size_t)pb * HH + kb);
#pragma unroll
                    for (int q = 0; q < 4; q++) hbuf[bl & 1][q] = __ldcg(hp + q);
                }
#pragma unroll
                for (int q = 0; q < 4; q++) {
                    ull av[4];
                    av[0] = pack2(hc[q].x, hc[q].x);
                    av[1] = pack2(hc[q].y, hc[q].y);
                    av[2] = pack2(hc[q].z, hc[q].z);
                    av[3] = pack2(hc[q].w, hc[q].w);
#pragma unroll
                    for (int kk = 0; kk < 4; kk++)
#pragma unroll
                        for (int p = 0; p < 4; p++)
                            acc[bl][p] = ffma2(av[kk], wreg[q * 4 + kk][p], acc[bl][p]);
                }
            }

            // ---- butterfly reduce over 8 kc-lanes (masks 16, 8, 4) ----
            float v[64];
#pragma unroll
            for (int bl = 0; bl < 8; bl++)
#pragma unroll
                for (int p = 0; p < 4; p++)
                    unpack2(acc[bl][p], v[bl * 8 + 2 * p], v[bl * 8 + 2 * p + 1]);

            float u1[32];
            {
                const bool bit = (lane & 16) != 0;
#pragma unroll
                for (int i = 0; i < 32; i++) {
                    const float send = bit ? v[i] : v[i + 32];
                    const float recv = __shfl_xor_sync(0xffffffffu, send, 16);
                    u1[i] = (bit ? v[i + 32] : v[i]) + recv;
                }
            }
            float u2[16];
            {
                const bool bit = (lane & 8) != 0;
#pragma unroll
                for (int i = 0; i < 16; i++) {
                    const float send = bit ? u1[i] : u1[i + 16];
                    const float recv = __shfl_xor_sync(0xffffffffu, send, 8);
                    u2[i] = (bit ? u1[i + 16] : u1[i]) + recv;
                }
            }
            float u3[8];
            {
                const bool bit = (lane & 4) != 0;
#pragma unroll
                for (int i = 0; i < 8; i++) {
                    const float send = bit ? u2[i] : u2[i + 8];
                    const float recv = __shfl_xor_sync(0xffffffffu, send, 4);
                    u3[i] = (bit ? u2[i + 8] : u2[i]) + recv;
                }
            }
            // lane now holds cols [cg*8..cg*8+8) of batch b = grp*8 + b_loc,
            // summed over its warp's 8 k-chunks
            float* rp = &red[wid * 288 + b_loc * 36 + cg * 8];
            *(float4*)rp       = make_float4(u3[0], u3[1], u3[2], u3[3]);
            *(float4*)(rp + 4) = make_float4(u3[4], u3[5], u3[6], u3[7]);
            __syncthreads();

            // ---- cross-warp reduce + x_proj add ----
            {
                const int ob = tid >> 5, oc = tid & 31;
                float gsum = 0.f;
#pragma unroll
                for (int w = 0; w < 8; w++) gsum += red[w * 288 + ob * 36 + oc];
                const int gate = oc >> 3, jl = oc & 7;
                const int b = grp * 8 + ob;
                gsum += __ldcs(&g_xproj[((size_t)t * BB + b) * G4 + gate * HH + j0 + jl]);
                gates[ob * 36 + oc] = gsum;
            }
            __syncthreads();

            // ---- LSTM cell (64 threads) ----
            if (tid < 64) {
                const int bl3 = tid >> 3, jl = tid & 7;
                const int b = grp * 8 + bl3;
                const float iv = sigf(gates[bl3 * 36 + jl]);
                const float fv = sigf(gates[bl3 * 36 + 8 + jl]);
                const float gv = tanhf(gates[bl3 * 36 + 16 + jl]);
                const float ov = sigf(gates[bl3 * 36 + 24 + jl]);
                const float cn = fmaf(fv, csm[b * 8 + jl], iv * gv);
                csm[b * 8 + jl] = cn;
                const float hv = ov * tanhf(cn);
                hdst[(size_t)b * HH + j0 + jl] = hv;
                out[((size_t)t * BB + b) * HH + j0 + jl] = hv;
            }
        }
        grid_barrier();
    }

    // ---- tail: h_T, c_T ----
    if (wr_tail && tid < 64) {
        const int bl3 = tid >> 3, jl = tid & 7;
        const float* hfin = g_h[(TS - 1) & 1];
#pragma unroll
        for (int grp = 0; grp < 8; grp++) {
            const int b = grp * 8 + bl3;
            out[hT + (size_t)b * HH + j0 + jl] = hfin[(size_t)b * HH + j0 + jl];
            out[hT + (size_t)BB * HH + (size_t)b * HH + j0 + jl] = csm[b * 8 + jl];
        }
    }
}

extern "C" void kernel_launch(void* const* d_in, const int* in_sizes, int n_in,
                              void* d_out, int out_size)
{
    const float* x   = (const float*)d_in[0];
    const float* Wih = (const float*)d_in[1];
    const float* Whh = (const float*)d_in[2];
    const float* bih = (const float*)d_in[3];
    const float* bhh = (const float*)d_in[4];
    const float* h0  = (const float*)d_in[5];
    const float* c0  = (const float*)d_in[6];
    float* out = (float*)d_out;

    dim3 g1(G4 / 128, (TS * BB) / 128);
    xproj_kernel<<<g1, 256>>>(x, Wih, bih, bhh);
    lstm_rec_kernel<<<128, 256>>>(Whh, h0, c0, out, out_size);
}

// round 5
// speedup vs baseline: 1.5423x; 1.0919x over previous
#include <cuda_runtime.h>
#include <cstdint>
#include <cstddef>

#define TS 1024
#define BB 64
#define HH 1024
#define G4 4096

__device__ float g_xproj[(size_t)TS * BB * G4];
__device__ float g_h[2][BB * HH];
__device__ unsigned g_count = 0;
__device__ unsigned g_gen = 0;

typedef unsigned long long ull;
__device__ __forceinline__ ull pack2(float a, float b) {
    ull r; asm("mov.b64 %0, {%1, %2};" : "=l"(r) : "f"(a), "f"(b)); return r;
}
__device__ __forceinline__ void unpack2(ull p, float& a, float& b) {
    asm("mov.b64 {%0, %1}, %2;" : "=f"(a), "=f"(b) : "l"(p));
}
__device__ __forceinline__ ull ffma2(ull a, ull b, ull c) {
    ull d; asm("fma.rn.f32x2 %0, %1, %2, %3;" : "=l"(d) : "l"(a), "l"(b), "l"(c)); return d;
}
__device__ __forceinline__ float sigf(float x) { return 1.0f / (1.0f + __expf(-x)); }

// ===================== Kernel 1: x_proj GEMM (128x128x16) =====================
__global__ __launch_bounds__(256) void xproj_kernel(
    const float* __restrict__ X, const float* __restrict__ Wih,
    const float* __restrict__ bih, const float* __restrict__ bhh)
{
    __shared__ float As[2][16][128];
    __shared__ float Bs[2][16][128];
    const int tid = threadIdx.x;
    const int m0 = blockIdx.y * 128, n0 = blockIdx.x * 128;
    const int lm = tid & 127, lq = tid >> 7;
    const float* Xrow = X + (size_t)(m0 + lm) * HH;
    const float* Wrow = Wih + (size_t)(n0 + lm) * HH;
    const int tx = tid & 15, ty = tid >> 4;

    ull acc[8][4];
#pragma unroll
    for (int r = 0; r < 8; r++)
#pragma unroll
        for (int j = 0; j < 4; j++) acc[r][j] = 0ull;

    float4 xa[2], xb[2];
#pragma unroll
    for (int u = 0; u < 2; u++) {
        xa[u] = *(const float4*)&Xrow[(lq + 2 * u) * 4];
        xb[u] = *(const float4*)&Wrow[(lq + 2 * u) * 4];
    }
    for (int kt = 0; kt < 64; ++kt) {
        const int cur = kt & 1;
#pragma unroll
        for (int u = 0; u < 2; u++) {
            const int kq = (lq + 2 * u) * 4;
            As[cur][kq + 0][lm] = xa[u].x; As[cur][kq + 1][lm] = xa[u].y;
            As[cur][kq + 2][lm] = xa[u].z; As[cur][kq + 3][lm] = xa[u].w;
            Bs[cur][kq + 0][lm] = xb[u].x; Bs[cur][kq + 1][lm] = xb[u].y;
            Bs[cur][kq + 2][lm] = xb[u].z; Bs[cur][kq + 3][lm] = xb[u].w;
        }
        __syncthreads();
        if (kt < 63) {
            const int kb = (kt + 1) * 16;
#pragma unroll
            for (int u = 0; u < 2; u++) {
                xa[u] = *(const float4*)&Xrow[kb + (lq + 2 * u) * 4];
                xb[u] = *(const float4*)&Wrow[kb + (lq + 2 * u) * 4];
            }
        }
#pragma unroll
        for (int k = 0; k < 16; k++) {
            const float4 a0 = *(const float4*)&As[cur][k][ty * 8];
            const float4 a1 = *(const float4*)&As[cur][k][ty * 8 + 4];
            const ulonglong2 b0 = *(const ulonglong2*)&Bs[cur][k][tx * 8];
            const ulonglong2 b1 = *(const ulonglong2*)&Bs[cur][k][tx * 8 + 4];
            const ull bp[4] = { b0.x, b0.y, b1.x, b1.y };
            const float av[8] = { a0.x, a0.y, a0.z, a0.w, a1.x, a1.y, a1.z, a1.w };
#pragma unroll
            for (int r = 0; r < 8; r++) {
                const ull ar = pack2(av[r], av[r]);
#pragma unroll
                for (int j = 0; j < 4; j++) acc[r][j] = ffma2(ar, bp[j], acc[r][j]);
            }
        }
        __syncthreads();
    }
    float bias[8];
#pragma unroll
    for (int j = 0; j < 8; j++) bias[j] = bih[n0 + tx * 8 + j] + bhh[n0 + tx * 8 + j];
#pragma unroll
    for (int r = 0; r < 8; r++) {
        float c[8];
        unpack2(acc[r][0], c[0], c[1]); unpack2(acc[r][1], c[2], c[3]);
        unpack2(acc[r][2], c[4], c[5]); unpack2(acc[r][3], c[6], c[7]);
        float* Crow = g_xproj + (size_t)(m0 + ty * 8 + r) * G4 + n0 + tx * 8;
#pragma unroll
        for (int j = 0; j < 8; j++) Crow[j] = c[j] + bias[j];
    }
}

// ===================== grid barrier =====================
__device__ __forceinline__ void grid_barrier()
{
    __syncthreads();
    if (threadIdx.x == 0) {
        __threadfence();
        const unsigned gen = *(volatile unsigned*)&g_gen;
        atomicAdd(&g_count, 1u);
        if (blockIdx.x == 0) {
            while (*(volatile unsigned*)&g_count != gridDim.x) { __nanosleep(64); }
            g_count = 0;
            __threadfence();
            atomicAdd(&g_gen, 1u);
        } else {
            while (*(volatile unsigned*)&g_gen == gen) { __nanosleep(64); }
        }
        __threadfence();
    }
    __syncthreads();
}

// ===================== Kernel 2: persistent recurrence, W in regs, no spills ==
// 128 CTAs x 256 threads. CTA bid owns h-cols [8*bid, 8*bid+8) => 32 gate cols.
// Thread (cg=tid&3, kc=tid>>2): gate cg, cols j0..j0+8, k-chunk [kc*16,+16).
// Per batch: 64 ffma2 -> 7-shuffle value-halving butterfly (final col =
// (lane>>2)&7) -> smem cross-warp sum -> quad allgather of 4 gates -> cell on
// gate-0 lane (c state in its registers).
__global__ __launch_bounds__(256, 1) void lstm_rec_kernel(
    const float* __restrict__ Whh, const float* __restrict__ h0,
    const float* __restrict__ c0, float* __restrict__ out, int out_size)
{
    __shared__ float red[2][8 * 8 * 32];   // [buf][bl][warp][lane]

    const int tid = threadIdx.x;
    const int j0 = blockIdx.x * 8;
    const int cg = tid & 3;
    const int kc = tid >> 2;
    const int kb = kc * 16;
    const int lane = tid & 31;
    const int wid = tid >> 5;
    const int jl = (lane >> 2) & 7;
    const bool writer = (cg == 0);

    // ---- W_hh slice into registers (once) ----
    ull wreg[16][4];
#pragma unroll
    for (int p = 0; p < 4; p++) {
        const float* r0 = Whh + (size_t)(cg * HH + j0 + 2 * p) * HH + kb;
        const float* r1 = r0 + HH;
        float w0[16], w1[16];
#pragma unroll
        for (int q = 0; q < 4; q++) {
            const float4 a = *(const float4*)&r0[q * 4];
            const float4 b4 = *(const float4*)&r1[q * 4];
            w0[q*4+0] = a.x;  w0[q*4+1] = a.y;  w0[q*4+2] = a.z;  w0[q*4+3] = a.w;
            w1[q*4+0] = b4.x; w1[q*4+1] = b4.y; w1[q*4+2] = b4.z; w1[q*4+3] = b4.w;
        }
#pragma unroll
        for (int k = 0; k < 16; k++) wreg[k][p] = pack2(w0[k], w1[k]);
    }

    // ---- c state in registers (meaningful on writer lanes) ----
    float c_reg[8];
#pragma unroll
    for (int grp = 0; grp < 8; grp++)
        c_reg[grp] = c0[(size_t)(grp * 8 + wid) * HH + j0 + jl];

    const int hT = TS * BB * HH;
    const bool wr_tail = out_size >= hT + 2 * BB * HH;

    for (int t = 0; t < TS; ++t) {
        const float* __restrict__ hsrc = (t == 0) ? h0 : g_h[(t + 1) & 1];
        float* __restrict__ hdst = g_h[t & 1];
        const float* __restrict__ xpt = g_xproj + (size_t)t * BB * G4;

        float4 hbuf[2][4];
#pragma unroll
        for (int u = 0; u < 2; u++) {
            const float4* hp = (const float4*)(hsrc + (size_t)u * HH + kb);
#pragma unroll
            for (int q = 0; q < 4; q++) hbuf[u][q] = __ldcg(hp + q);
        }

        for (int grp = 0; grp < 8; ++grp) {
            const float xpv =
                __ldcs(&xpt[(size_t)(grp * 8 + wid) * G4 + cg * HH + j0 + jl]);
            float* redb = red[grp & 1];

#pragma unroll
            for (int bl = 0; bl < 8; bl++) {
                float4 hc[4];
#pragma unroll
                for (int q = 0; q < 4; q++) hc[q] = hbuf[bl & 1][q];
                const int pb = grp * 8 + bl + 2;
                if (pb < BB) {
                    const float4* hp = (const float4*)(hsrc + (size_t)pb * HH + kb);
#pragma unroll
                    for (int q = 0; q < 4; q++) hbuf[bl & 1][q] = __ldcg(hp + q);
                }

                ull acc[4] = {0ull, 0ull, 0ull, 0ull};
#pragma unroll
                for (int q = 0; q < 4; q++) {
                    ull av[4];
                    av[0] = pack2(hc[q].x, hc[q].x);
                    av[1] = pack2(hc[q].y, hc[q].y);
                    av[2] = pack2(hc[q].z, hc[q].z);
                    av[3] = pack2(hc[q].w, hc[q].w);
#pragma unroll
                    for (int kk = 0; kk < 4; kk++)
#pragma unroll
                        for (int p = 0; p < 4; p++)
                            acc[p] = ffma2(av[kk], wreg[q * 4 + kk][p], acc[p]);
                }

                // ---- value-halving butterfly over 8 kc-lanes ----
                float v[8];
                unpack2(acc[0], v[0], v[1]); unpack2(acc[1], v[2], v[3]);
                unpack2(acc[2], v[4], v[5]); unpack2(acc[3], v[6], v[7]);

                float u4[4];
                {
                    const bool bit = (lane & 16) != 0;
#pragma unroll
                    for (int i = 0; i < 4; i++) {
                        const float send = bit ? v[i] : v[i + 4];
                        const float recv = __shfl_xor_sync(0xffffffffu, send, 16);
                        u4[i] = (bit ? v[i + 4] : v[i]) + recv;
                    }
                }
                float u2a[2];
                {
                    const bool bit = (lane & 8) != 0;
#pragma unroll
                    for (int i = 0; i < 2; i++) {
                        const float send = bit ? u4[i] : u4[i + 2];
                        const float recv = __shfl_xor_sync(0xffffffffu, send, 8);
                        u2a[i] = (bit ? u4[i + 2] : u4[i]) + recv;
                    }
                }
                float rsum;
                {
                    const bool bit = (lane & 4) != 0;
                    const float send = bit ? u2a[0] : u2a[1];
                    const float recv = __shfl_xor_sync(0xffffffffu, send, 4);
                    rsum = (bit ? u2a[1] : u2a[0]) + recv;
                }
                redb[(bl * 8 + wid) * 32 + lane] = rsum;
            }
            __syncthreads();

            // ---- cross-warp sum: warp wid handles batch grp*8+wid ----
            float gsum = xpv;
#pragma unroll
            for (int w = 0; w < 8; w++)
                gsum += redb[(wid * 8 + w) * 32 + lane];

            const float act = (cg == 2) ? tanhf(gsum) : sigf(gsum);
            const float a1 = __shfl_xor_sync(0xffffffffu, act, 1);
            const float a2 = __shfl_xor_sync(0xffffffffu, act, 2);
            const float a3 = __shfl_xor_sync(0xffffffffu, a1, 2);

            if (writer) {
                // on cg==0 lane: act=i, a1=f, a2=g, a3=o
                const float cn = fmaf(a1, c_reg[grp], act * a2);
                c_reg[grp] = cn;
                const float hv = a3 * tanhf(cn);
                const int b = grp * 8 + wid;
                hdst[(size_t)b * HH + j0 + jl] = hv;
                out[((size_t)t * BB + b) * HH + j0 + jl] = hv;
            }
        }
        grid_barrier();
    }

    if (wr_tail && writer) {
        const float* hfin = g_h[(TS - 1) & 1];
#pragma unroll
        for (int grp = 0; grp < 8; grp++) {
            const int b = grp * 8 + wid;
            out[hT + (size_t)b * HH + j0 + jl] = hfin[(size_t)b * HH + j0 + jl];
            out[hT + BB * HH + (size_t)b * HH + j0 + jl] = c_reg[grp];
        }
    }
}

extern "C" void kernel_launch(void* const* d_in, const int* in_sizes, int n_in,
                              void* d_out, int out_size)
{
    const float* x   = (const float*)d_in[0];
    const float* Wih = (const float*)d_in[1];
    const float* Whh = (const float*)d_in[2];
    const float* bih = (const float*)d_in[3];
    const float* bhh = (const float*)d_in[4];
    const float* h0  = (const float*)d_in[5];
    const float* c0  = (const float*)d_in[6];
    float* out = (float*)d_out;

    dim3 g1(G4 / 128, (TS * BB) / 128);
    xproj_kernel<<<g1, 256>>>(x, Wih, bih, bhh);
    lstm_rec_kernel<<<128, 256>>>(Whh, h0, c0, out, out_size);
}